// round 13
// baseline (speedup 1.0000x reference)
#include <cuda_runtime.h>
#include <cuda_fp16.h>
#include <cstdint>

#define NN 500000
#define NE 16000000
#define PROBE_N 1000000

#define ZT 32768                    // src-tile nodes (64 KB fp16), power of 2
#define ZSH 15
#define NT 16                       // 16*32768 = 524288 >= NN
#define ZPAD (ZT * NT)
#define M2 (NT * NN)                // (tile,dst) counters = 8,000,000

#define BLK_S 1024
#define PD 19
#define CS (BLK_S * PD)             // 19456 dsts per chunk
#define NCHUNK 26                   // 26*19456 >= NN
#define NBLOCKS (NT * NCHUNK)       // 416 spmv CTAs
#define NRUNS (NBLOCKS * BLK_S)     // 425984 thread-runs
#define NRB (NRUNS / 1024)          // 416 scan blocks (exact)
#define E16LEN (NE + 8 * NRUNS)     // padded edge array (runs 8-aligned)

#define SMEM_S (ZT * 2 + CS * 2)    // 65536 + 38912 = 104448 B -> 2 CTAs/SM

// -------- device scratch (no allocations allowed in kernel_launch) ----------
__device__ int      g_hi_nonzero;   // 0 => adj is int64 (hi words all zero)
__device__ int      g_cnt2[M2];     // per-(tile,dst) edge counts
__device__ int      g_cursor2[M2];  // scatter cursors (abs padded positions)
__device__ uint8_t  g_cnt8T[NBLOCKS * CS];  // transposed counts
__device__ int      g_runlenp[NRUNS];       // padded run lengths
__device__ int      g_sR[NRUNS];
__device__ int      g_runstart[NRUNS];
__device__ int      g_bsumR[NRB];
__device__ int      g_bexclR[NRB];
__device__ float    g_dis[NN];
__device__ __half   g_part[M2];     // per-(tile,dst) partials : 16 MB
__device__ uint16_t g_e16[E16LEN];  // padded edges : ~39 MB
__device__ __half   g_za[ZPAD];
__device__ __half   g_zb[ZPAD];

// ----------------------------- cp.async helpers ------------------------------
__device__ __forceinline__ void cp_async16(void* sdst, const void* gsrc) {
    uint32_t s = (uint32_t)__cvta_generic_to_shared(sdst);
    asm volatile("cp.async.cg.shared.global [%0], [%1], 16;\n" :: "r"(s), "l"(gsrc));
}
__device__ __forceinline__ void cp_commit() {
    asm volatile("cp.async.commit_group;\n" ::);
}
template <int N>
__device__ __forceinline__ void cp_wait() {
    asm volatile("cp.async.wait_group %0;\n" :: "n"(N));
}

// ----------------------------- init + probe ----------------------------------
__global__ void init_kernel() {
    int i = blockIdx.x * blockDim.x + threadIdx.x;
    if (i == 0) g_hi_nonzero = 0;
    if (i < M2) g_cnt2[i] = 0;
}

__global__ void probe_kernel(const int* __restrict__ adj32) {
    int i = blockIdx.x * blockDim.x + threadIdx.x;
    int v = (i < PROBE_N) ? adj32[2 * i + 1] : 0;
    #pragma unroll
    for (int o = 16; o > 0; o >>= 1) v |= __shfl_down_sync(0xffffffffu, v, o);
    if ((threadIdx.x & 31) == 0 && v) atomicOr(&g_hi_nonzero, 1);
}

// ----------------------------- precompute -----------------------------------
__global__ void count2_kernel(const int* __restrict__ adj) {
    int e = blockIdx.x * blockDim.x + threadIdx.x;
    if (e >= NE) return;
    int s, d;
    if (g_hi_nonzero == 0) {
        s = ((const int2*)adj)[e].x;
        d = ((const int2*)adj)[NE + e].x;
    } else {
        s = adj[e];
        d = adj[NE + e];
    }
    atomicAdd(&g_cnt2[(s >> ZSH) * NN + d], 1);
}

__global__ void dis_kernel(const float* __restrict__ x0) {
    int v = blockIdx.x * blockDim.x + threadIdx.x;
    if (v >= NN) return;
    int deg = 0;
    #pragma unroll
    for (int t = 0; t < NT; t++) deg += g_cnt2[t * NN + v];
    float di = rsqrtf((float)(deg + 1));  // +1 self-loop
    g_dis[v] = di;
    g_za[v]  = __float2half(di * x0[v]);
}

// One thread per run: local prefix over its <=19 dsts -> cursor2 (run-local),
// transposed counts, padded run length.
__global__ void runprep_kernel() {
    int r = blockIdx.x * blockDim.x + threadIdx.x;
    if (r >= NRUNS) return;
    int block = r / BLK_S;
    int tid   = r - block * BLK_S;
    int t = block / NCHUNK;
    int c = block - t * NCHUNK;
    int dbeg = c * CS + tid * PD;
    int base = t * NN;
    int run = 0;
    #pragma unroll 1
    for (int k = 0; k < PD; k++) {
        int d = dbeg + k;
        int cnt = (d < NN) ? g_cnt2[base + d] : 0;
        if (d < NN) g_cursor2[base + d] = run;       // run-local prefix
        g_cnt8T[block * CS + k * BLK_S + tid] = (uint8_t)cnt;
        run += cnt;
    }
    g_runlenp[r] = (run + 7) & ~7;                   // pad to 8 (16B) alignment
}

// generic per-block inclusive scan (1024)
__global__ void scan_blk_kernel(const int* __restrict__ in, int* __restrict__ out,
                                int* __restrict__ bsum, int m) {
    __shared__ int sm[1024];
    int t = threadIdx.x;
    int gid = blockIdx.x * 1024 + t;
    int v = (gid < m) ? in[gid] : 0;
    sm[t] = v;
    __syncthreads();
    for (int off = 1; off < 1024; off <<= 1) {
        int tmp = (t >= off) ? sm[t - off] : 0;
        __syncthreads();
        sm[t] += tmp;
        __syncthreads();
    }
    if (gid < m) out[gid] = sm[t];
    if (t == 1023) bsum[blockIdx.x] = sm[1023];
}

__global__ void scan_tiny_kernel(const int* __restrict__ in, int* __restrict__ outExcl, int m) {
    if (threadIdx.x == 0 && blockIdx.x == 0) {
        int run = 0;
        for (int j = 0; j < m; j++) { outExcl[j] = run; run += in[j]; }
    }
}

__global__ void runfix_kernel() {
    int r = blockIdx.x * blockDim.x + threadIdx.x;
    if (r < NRUNS)
        g_runstart[r] = g_sR[r] - g_runlenp[r] + g_bexclR[r >> 10];
}

// cursor2[g] += runstart(run containing g)  -> absolute padded positions
__global__ void cursorfix_kernel() {
    int g = blockIdx.x * blockDim.x + threadIdx.x;
    if (g >= M2) return;
    int t = g / NN;
    int d = g - t * NN;
    int c = d / CS;
    int l = d - c * CS;
    int r = (t * NCHUNK + c) * BLK_S + l / PD;
    g_cursor2[g] += g_runstart[r];
}

__global__ void scatter16_kernel(const int* __restrict__ adj) {
    int e = blockIdx.x * blockDim.x + threadIdx.x;
    if (e >= NE) return;
    int s, d;
    if (g_hi_nonzero == 0) {
        s = ((const int2*)adj)[e].x;
        d = ((const int2*)adj)[NE + e].x;
    } else {
        s = adj[e];
        d = adj[NE + e];
    }
    int t = s >> ZSH;
    int pos = atomicAdd(&g_cursor2[t * NN + d], 1);
    g_e16[pos] = (uint16_t)(s & (ZT - 1));
}

// ------------------------------ spmv kernel ---------------------------------
// CTA = (tile t, chunk c). Stage z-tile (64 KB). Thread owns 19 consecutive
// dsts whose padded edge-run starts 16B-aligned at g_runstart[r]; walk with
// aligned uint4 loads, consuming counts from transposed cnt8T (coalesced).
// Partials -> smem fp16 (linear-in-d layout) -> coalesced copy-out. No atomics.
__global__ void __launch_bounds__(BLK_S, 2)
spmv_kernel(int cur_sel)
{
    extern __shared__ char sh[];
    __half* zt   = (__half*)sh;
    __half* part = (__half*)(sh + ZT * 2);

    int block = blockIdx.x;
    int t = block / NCHUNK;
    int c = block - t * NCHUNK;
    int tid = threadIdx.x;

    const __half* __restrict__ zg = cur_sel ? g_zb : g_za;

    // stage tile t (64 KB)
    {
        const char* src = (const char*)(zg + t * ZT);
        #pragma unroll
        for (int i = 0; i < 4; i++) {
            int o = (i * BLK_S + tid) * 16;
            cp_async16(sh + o, src + o);
        }
        cp_commit();
    }

    int e0 = g_runstart[block * BLK_S + tid];        // 8-aligned
    const uint4* ev = (const uint4*)g_e16 + (e0 >> 3);
    const uint8_t* cp = g_cnt8T + block * CS + tid;

    cp_wait<0>();
    __syncthreads();

    {
        int j = 0;
        uint4 u;
        int pbase = tid * PD;
        #pragma unroll 1
        for (int k = 0; k < PD; k++) {
            int cnt = cp[k * BLK_S];
            float a = 0.0f;
            for (int i = 0; i < cnt; i++, j++) {
                int slot = j & 7;
                if (slot == 0) u = __ldg(&ev[j >> 3]);
                uint32_t wv = (slot < 4) ? ((slot < 2) ? u.x : u.y)
                                         : ((slot < 6) ? u.z : u.w);
                int lsrc = (wv >> ((j & 1) << 4)) & 0xFFFF;
                a += __half2float(zt[lsrc]);
            }
            part[pbase + k] = __float2half(a);
        }
    }
    __syncthreads();

    // coalesced copy-out: partials (linear in d) -> g_part[t][cbase..cend)
    {
        int cbase = c * CS;
        int cend  = min(cbase + CS, NN);
        int nwords = (cend - cbase) >> 1;            // even
        const uint32_t* ps = (const uint32_t*)part;
        uint32_t* pg = (uint32_t*)(g_part + t * NN + cbase);
        for (int i = tid; i < nwords; i += BLK_S) pg[i] = ps[i];
    }
}

// ------------------------------ combine kernel -------------------------------
// acc = sum_t part[t][v]; h = dis*(acc + z_self); y = (0.7h + 0.3 x0)*w;
// z' = dis*act(y).  act: 0=id 1=leaky 2=sigmoid 3=relu 4=final
__global__ void combine_kernel(const float* __restrict__ x0,
                               const float* __restrict__ w,
                               float* __restrict__ out,
                               int layer, int act, int cur_sel)
{
    int v0 = (blockIdx.x * blockDim.x + threadIdx.x) * 4;
    if (v0 >= NN) return;   // NN % 4 == 0

    const __half* __restrict__ zg = cur_sel ? g_zb : g_za;

    float a0 = 0.f, a1 = 0.f, a2 = 0.f, a3 = 0.f;
    #pragma unroll
    for (int t = 0; t < NT; t++) {
        const __half* p = &g_part[t * NN + v0];
        __half2 p01 = *(const __half2*)p;
        __half2 p23 = *(const __half2*)(p + 2);
        a0 += __half2float(p01.x);  a1 += __half2float(p01.y);
        a2 += __half2float(p23.x);  a3 += __half2float(p23.y);
    }

    float4 dv = *(const float4*)&g_dis[v0];
    float4 xv = *(const float4*)&x0[v0];
    __half2 zs01 = *(const __half2*)&zg[v0];
    __half2 zs23 = *(const __half2*)&zg[v0 + 2];
    float wl = __ldg(&w[layer]);

    float h0 = dv.x * (a0 + __half2float(zs01.x));
    float h1 = dv.y * (a1 + __half2float(zs01.y));
    float h2 = dv.z * (a2 + __half2float(zs23.x));
    float h3 = dv.w * (a3 + __half2float(zs23.y));
    float y0 = (0.7f * h0 + 0.3f * xv.x) * wl;
    float y1 = (0.7f * h1 + 0.3f * xv.y) * wl;
    float y2 = (0.7f * h2 + 0.3f * xv.z) * wl;
    float y3 = (0.7f * h3 + 0.3f * xv.w) * wl;

    if (act == 4) {
        // astype(int) truncates toward zero; value < 2^24 -> exact in fp32.
        float4 o;
        o.x = truncf(500000.0f / (1.0f + expf(-y0)));
        o.y = truncf(500000.0f / (1.0f + expf(-y1)));
        o.z = truncf(500000.0f / (1.0f + expf(-y2)));
        o.w = truncf(500000.0f / (1.0f + expf(-y3)));
        *(float4*)&out[v0] = o;
        return;
    }
    float r0, r1, r2, r3;
    if      (act == 0) { r0 = y0; r1 = y1; r2 = y2; r3 = y3; }
    else if (act == 1) {
        r0 = (y0 > 0.f) ? y0 : 0.01f * y0;  r1 = (y1 > 0.f) ? y1 : 0.01f * y1;
        r2 = (y2 > 0.f) ? y2 : 0.01f * y2;  r3 = (y3 > 0.f) ? y3 : 0.01f * y3;
    } else if (act == 2) {
        r0 = 1.0f / (1.0f + expf(-y0));  r1 = 1.0f / (1.0f + expf(-y1));
        r2 = 1.0f / (1.0f + expf(-y2));  r3 = 1.0f / (1.0f + expf(-y3));
    } else {
        r0 = fmaxf(y0, 0.f); r1 = fmaxf(y1, 0.f);
        r2 = fmaxf(y2, 0.f); r3 = fmaxf(y3, 0.f);
    }

    __half* zn = cur_sel ? g_za : g_zb;
    *(__half2*)&zn[v0]     = __floats2half2_rn(dv.x * r0, dv.y * r1);
    *(__half2*)&zn[v0 + 2] = __floats2half2_rn(dv.z * r2, dv.w * r3);
}

// ------------------------------- host entry ---------------------------------
extern "C" void kernel_launch(void* const* d_in, const int* in_sizes, int n_in,
                              void* d_out, int out_size)
{
    const float* input = nullptr;
    const float* w     = nullptr;
    const int*   adj   = nullptr;
    for (int i = 0; i < n_in; i++) {
        if      (in_sizes[i] == 49) w     = (const float*)d_in[i];
        else if (in_sizes[i] == NN) input = (const float*)d_in[i];
        else                        adj   = (const int*)d_in[i];
    }
    float* out = (float*)d_out;

    cudaFuncSetAttribute(spmv_kernel,
                         cudaFuncAttributeMaxDynamicSharedMemorySize, SMEM_S);

    int nb_m2    = (M2 + 255) / 256;
    int nb_nodes = (NN + 255) / 256;
    int nb_edges = (NE + 255) / 256;
    int nb_probe = (PROBE_N + 255) / 256;
    int nb_runs  = (NRUNS + 255) / 256;

    init_kernel     <<<nb_m2, 256>>>();
    probe_kernel    <<<nb_probe, 256>>>(adj);
    count2_kernel   <<<nb_edges, 256>>>(adj);
    dis_kernel      <<<nb_nodes, 256>>>(input);
    runprep_kernel  <<<nb_runs, 256>>>();
    scan_blk_kernel <<<NRB, 1024>>>(g_runlenp, g_sR, g_bsumR, NRUNS);
    scan_tiny_kernel<<<1, 32>>>(g_bsumR, g_bexclR, NRB);
    runfix_kernel   <<<nb_runs, 256>>>();
    cursorfix_kernel<<<nb_m2, 256>>>();
    scatter16_kernel<<<nb_edges, 256>>>(adj);

    int nb_comb = (NN / 4 + 255) / 256;
    int cur = 0;   // z0 lives in g_za
    for (int i = 0; i < 49; i++) {
        int act;
        if      (i == 48) act = 4;
        else if (i == 0)  act = 0;
        else if (i == 1 || i == 11 || i == 21 || i == 31 || i == 41) act = 1;
        else if (i == 4 || i == 14 || i == 24 || i == 34 || i == 44) act = 2;
        else act = 3;
        spmv_kernel   <<<NBLOCKS, BLK_S, SMEM_S>>>(cur);
        combine_kernel<<<nb_comb, 256>>>(input, w, out, i, act, cur);
        cur ^= 1;
    }
}

// round 14
// speedup vs baseline: 1.2686x; 1.2686x over previous
#include <cuda_runtime.h>
#include <cuda_fp16.h>
#include <cstdint>

#define NN 500000
#define NE 16000000
#define PROBE_N 1000000

#define ZT 32768                    // src-tile nodes (64 KB fp16), power of 2
#define ZSH 15
#define NT 16                       // 16*32768 >= NN
#define ZPAD (ZT * NT)
#define M2 (NT * NN)                // (tile,dst) counters = 8,000,000

#define BLK_S 1024
#define PD 19
#define CS (BLK_S * PD)             // 19456 dsts per chunk
#define NCHUNK 26                   // 26*19456 >= NN
#define NBLOCKS (NT * NCHUNK)       // 416 spmv CTAs
#define NRUNS (NBLOCKS * BLK_S)     // 425984 thread-runs
#define NRB (NRUNS / 1024)          // 416 scan blocks (exact)
#define E16LEN (NE + 8 * NRUNS)     // padded edge array (runs 8-aligned)

#define SMEM_S (ZT * 2 + CS * 2)    // 65536 + 38912 = 104448 B -> 2 CTAs/SM

// -------- device scratch (no allocations allowed in kernel_launch) ----------
__device__ int      g_hi_nonzero;   // 0 => adj is int64 (hi words all zero)
__device__ int      g_cnt2[M2];     // per-(tile,dst) edge counts
__device__ int      g_cursor2[M2];  // scatter cursors (abs padded positions)
__device__ uint8_t  g_cnt8T[NBLOCKS * CS];  // transposed counts
__device__ int      g_runlenp[NRUNS];       // padded run lengths
__device__ int      g_runlen[NRUNS];        // real run lengths
__device__ int      g_sR[NRUNS];
__device__ int      g_runstart[NRUNS];
__device__ int      g_bsumR[NRB];
__device__ int      g_bexclR[NRB];
__device__ float    g_dis[NN];
__device__ __half   g_part[M2];     // per-(tile,dst) partials : 16 MB
__device__ uint16_t g_e16[E16LEN];  // padded edges : ~39 MB
__device__ __half   g_za[ZPAD];
__device__ __half   g_zb[ZPAD];

// ----------------------------- cp.async helpers ------------------------------
__device__ __forceinline__ void cp_async16(void* sdst, const void* gsrc) {
    uint32_t s = (uint32_t)__cvta_generic_to_shared(sdst);
    asm volatile("cp.async.cg.shared.global [%0], [%1], 16;\n" :: "r"(s), "l"(gsrc));
}
__device__ __forceinline__ void cp_commit() {
    asm volatile("cp.async.commit_group;\n" ::);
}
template <int N>
__device__ __forceinline__ void cp_wait() {
    asm volatile("cp.async.wait_group %0;\n" :: "n"(N));
}

// ----------------------------- init + probe ----------------------------------
__global__ void init_kernel() {
    int i = blockIdx.x * blockDim.x + threadIdx.x;
    if (i == 0) g_hi_nonzero = 0;
    if (i < M2) g_cnt2[i] = 0;
}

__global__ void probe_kernel(const int* __restrict__ adj32) {
    int i = blockIdx.x * blockDim.x + threadIdx.x;
    int v = (i < PROBE_N) ? adj32[2 * i + 1] : 0;
    #pragma unroll
    for (int o = 16; o > 0; o >>= 1) v |= __shfl_down_sync(0xffffffffu, v, o);
    if ((threadIdx.x & 31) == 0 && v) atomicOr(&g_hi_nonzero, 1);
}

// ----------------------------- precompute -----------------------------------
__global__ void count2_kernel(const int* __restrict__ adj) {
    int e = blockIdx.x * blockDim.x + threadIdx.x;
    if (e >= NE) return;
    int s, d;
    if (g_hi_nonzero == 0) {
        s = ((const int2*)adj)[e].x;
        d = ((const int2*)adj)[NE + e].x;
    } else {
        s = adj[e];
        d = adj[NE + e];
    }
    atomicAdd(&g_cnt2[(s >> ZSH) * NN + d], 1);
}

__global__ void dis_kernel(const float* __restrict__ x0) {
    int v = blockIdx.x * blockDim.x + threadIdx.x;
    if (v >= NN) return;
    int deg = 0;
    #pragma unroll
    for (int t = 0; t < NT; t++) deg += g_cnt2[t * NN + v];
    float di = rsqrtf((float)(deg + 1));  // +1 self-loop
    g_dis[v] = di;
    g_za[v]  = __float2half(di * x0[v]);
}

// One thread per run: local prefix over its <=19 dsts -> cursor2 (run-local),
// transposed counts, padded+real run lengths.
__global__ void runprep_kernel() {
    int r = blockIdx.x * blockDim.x + threadIdx.x;
    if (r >= NRUNS) return;
    int block = r / BLK_S;
    int tid   = r - block * BLK_S;
    int t = block / NCHUNK;
    int c = block - t * NCHUNK;
    int dbeg = c * CS + tid * PD;
    int base = t * NN;
    int run = 0;
    #pragma unroll 1
    for (int k = 0; k < PD; k++) {
        int d = dbeg + k;
        int cnt = (d < NN) ? g_cnt2[base + d] : 0;
        if (d < NN) g_cursor2[base + d] = run;       // run-local prefix
        g_cnt8T[block * CS + k * BLK_S + tid] = (uint8_t)cnt;
        run += cnt;
    }
    g_runlen[r]  = run;
    g_runlenp[r] = (run + 7) & ~7;                   // pad to 8 (16B) alignment
}

// generic per-block inclusive scan (1024)
__global__ void scan_blk_kernel(const int* __restrict__ in, int* __restrict__ out,
                                int* __restrict__ bsum, int m) {
    __shared__ int sm[1024];
    int t = threadIdx.x;
    int gid = blockIdx.x * 1024 + t;
    int v = (gid < m) ? in[gid] : 0;
    sm[t] = v;
    __syncthreads();
    for (int off = 1; off < 1024; off <<= 1) {
        int tmp = (t >= off) ? sm[t - off] : 0;
        __syncthreads();
        sm[t] += tmp;
        __syncthreads();
    }
    if (gid < m) out[gid] = sm[t];
    if (t == 1023) bsum[blockIdx.x] = sm[1023];
}

__global__ void scan_tiny_kernel(const int* __restrict__ in, int* __restrict__ outExcl, int m) {
    if (threadIdx.x == 0 && blockIdx.x == 0) {
        int run = 0;
        for (int j = 0; j < m; j++) { outExcl[j] = run; run += in[j]; }
    }
}

__global__ void runfix_kernel() {
    int r = blockIdx.x * blockDim.x + threadIdx.x;
    if (r < NRUNS)
        g_runstart[r] = g_sR[r] - g_runlenp[r] + g_bexclR[r >> 10];
}

// cursor2[g] += runstart(run containing g)  -> absolute padded positions
__global__ void cursorfix_kernel() {
    int g = blockIdx.x * blockDim.x + threadIdx.x;
    if (g >= M2) return;
    int t = g / NN;
    int d = g - t * NN;
    int c = d / CS;
    int l = d - c * CS;
    int r = (t * NCHUNK + c) * BLK_S + l / PD;
    g_cursor2[g] += g_runstart[r];
}

__global__ void scatter16_kernel(const int* __restrict__ adj) {
    int e = blockIdx.x * blockDim.x + threadIdx.x;
    if (e >= NE) return;
    int s, d;
    if (g_hi_nonzero == 0) {
        s = ((const int2*)adj)[e].x;
        d = ((const int2*)adj)[NE + e].x;
    } else {
        s = adj[e];
        d = adj[NE + e];
    }
    int t = s >> ZSH;
    int pos = atomicAdd(&g_cursor2[t * NN + d], 1);
    g_e16[pos] = (uint16_t)(s & (ZT - 1));
}

// ------------------------------ spmv kernel ---------------------------------
// CTA = (tile t, chunk c). Stage z-tile (64 KB). Thread owns 19 consecutive
// dsts whose padded edge-run starts 16B-aligned; walk real length with
// aligned uint4 body + scalar tail (R12 emit-walker), consuming counts from
// transposed cnt8T. Partials -> smem fp16 -> coalesced copy-out. No atomics.
__global__ void __launch_bounds__(BLK_S, 2)
spmv_kernel(int cur_sel)
{
    extern __shared__ char sh[];
    __half* zt   = (__half*)sh;
    __half* part = (__half*)(sh + ZT * 2);

    int block = blockIdx.x;
    int t = block / NCHUNK;
    int c = block - t * NCHUNK;
    int tid = threadIdx.x;

    const __half* __restrict__ zg = cur_sel ? g_zb : g_za;

    // stage tile t (64 KB)
    {
        const char* src = (const char*)(zg + t * ZT);
        #pragma unroll
        for (int i = 0; i < 4; i++) {
            int o = (i * BLK_S + tid) * 16;
            cp_async16(sh + o, src + o);
        }
        cp_commit();
    }

    int r   = block * BLK_S + tid;
    int e0  = g_runstart[r];         // 8-aligned
    int len = g_runlen[r];           // real edge count of this run
    const uint8_t* cp = g_cnt8T + block * CS + tid;

    cp_wait<0>();
    __syncthreads();

    {
        int   pbase = tid * PD;
        int   k   = 0;
        int   cnt = cp[0];
        float a   = 0.0f;

        auto emit = [&](int lsrc) {
            while (cnt == 0) {       // flush dst, advance (handles empty dsts)
                part[pbase + k] = __float2half(a);
                a = 0.0f;
                k++;
                cnt = cp[k * BLK_S];
            }
            a += __half2float(zt[lsrc]);
            cnt--;
        };

        const uint4* ev = (const uint4*)g_e16 + (e0 >> 3);
        int ng = len >> 3;
        for (int gi = 0; gi < ng; gi++) {
            uint4 u = __ldg(&ev[gi]);
            emit(u.x & 0xFFFF); emit(u.x >> 16);
            emit(u.y & 0xFFFF); emit(u.y >> 16);
            emit(u.z & 0xFFFF); emit(u.z >> 16);
            emit(u.w & 0xFFFF); emit(u.w >> 16);
        }
        for (int j = ng << 3; j < len; j++)
            emit(__ldg(&g_e16[e0 + j]));

        // flush current dst and zero-fill the rest
        for (;;) {
            part[pbase + k] = __float2half(a);
            a = 0.0f;
            k++;
            if (k >= PD) break;
        }
    }
    __syncthreads();

    // coalesced copy-out: partials (linear in d) -> g_part[t][cbase..cend)
    {
        int cbase = c * CS;
        int cend  = min(cbase + CS, NN);
        int nwords = (cend - cbase) >> 1;            // even
        const uint32_t* ps = (const uint32_t*)part;
        uint32_t* pg = (uint32_t*)(g_part + t * NN + cbase);
        for (int i = tid; i < nwords; i += BLK_S) pg[i] = ps[i];
    }
}

// ------------------------------ combine kernel -------------------------------
// acc = sum_t part[t][v]; h = dis*(acc + z_self); y = (0.7h + 0.3 x0)*w;
// z' = dis*act(y).  act: 0=id 1=leaky 2=sigmoid 3=relu 4=final
__global__ void combine_kernel(const float* __restrict__ x0,
                               const float* __restrict__ w,
                               float* __restrict__ out,
                               int layer, int act, int cur_sel)
{
    int v0 = (blockIdx.x * blockDim.x + threadIdx.x) * 4;
    if (v0 >= NN) return;   // NN % 4 == 0

    const __half* __restrict__ zg = cur_sel ? g_zb : g_za;

    float a0 = 0.f, a1 = 0.f, a2 = 0.f, a3 = 0.f;
    #pragma unroll
    for (int t = 0; t < NT; t++) {
        const __half* p = &g_part[t * NN + v0];
        __half2 p01 = *(const __half2*)p;
        __half2 p23 = *(const __half2*)(p + 2);
        a0 += __half2float(p01.x);  a1 += __half2float(p01.y);
        a2 += __half2float(p23.x);  a3 += __half2float(p23.y);
    }

    float4 dv = *(const float4*)&g_dis[v0];
    float4 xv = *(const float4*)&x0[v0];
    __half2 zs01 = *(const __half2*)&zg[v0];
    __half2 zs23 = *(const __half2*)&zg[v0 + 2];
    float wl = __ldg(&w[layer]);

    float h0 = dv.x * (a0 + __half2float(zs01.x));
    float h1 = dv.y * (a1 + __half2float(zs01.y));
    float h2 = dv.z * (a2 + __half2float(zs23.x));
    float h3 = dv.w * (a3 + __half2float(zs23.y));
    float y0 = (0.7f * h0 + 0.3f * xv.x) * wl;
    float y1 = (0.7f * h1 + 0.3f * xv.y) * wl;
    float y2 = (0.7f * h2 + 0.3f * xv.z) * wl;
    float y3 = (0.7f * h3 + 0.3f * xv.w) * wl;

    if (act == 4) {
        // astype(int) truncates toward zero; value < 2^24 -> exact in fp32.
        float4 o;
        o.x = truncf(500000.0f / (1.0f + expf(-y0)));
        o.y = truncf(500000.0f / (1.0f + expf(-y1)));
        o.z = truncf(500000.0f / (1.0f + expf(-y2)));
        o.w = truncf(500000.0f / (1.0f + expf(-y3)));
        *(float4*)&out[v0] = o;
        return;
    }
    float r0, r1, r2, r3;
    if      (act == 0) { r0 = y0; r1 = y1; r2 = y2; r3 = y3; }
    else if (act == 1) {
        r0 = (y0 > 0.f) ? y0 : 0.01f * y0;  r1 = (y1 > 0.f) ? y1 : 0.01f * y1;
        r2 = (y2 > 0.f) ? y2 : 0.01f * y2;  r3 = (y3 > 0.f) ? y3 : 0.01f * y3;
    } else if (act == 2) {
        r0 = 1.0f / (1.0f + expf(-y0));  r1 = 1.0f / (1.0f + expf(-y1));
        r2 = 1.0f / (1.0f + expf(-y2));  r3 = 1.0f / (1.0f + expf(-y3));
    } else {
        r0 = fmaxf(y0, 0.f); r1 = fmaxf(y1, 0.f);
        r2 = fmaxf(y2, 0.f); r3 = fmaxf(y3, 0.f);
    }

    __half* zn = cur_sel ? g_za : g_zb;
    *(__half2*)&zn[v0]     = __floats2half2_rn(dv.x * r0, dv.y * r1);
    *(__half2*)&zn[v0 + 2] = __floats2half2_rn(dv.z * r2, dv.w * r3);
}

// ------------------------------- host entry ---------------------------------
extern "C" void kernel_launch(void* const* d_in, const int* in_sizes, int n_in,
                              void* d_out, int out_size)
{
    const float* input = nullptr;
    const float* w     = nullptr;
    const int*   adj   = nullptr;
    for (int i = 0; i < n_in; i++) {
        if      (in_sizes[i] == 49) w     = (const float*)d_in[i];
        else if (in_sizes[i] == NN) input = (const float*)d_in[i];
        else                        adj   = (const int*)d_in[i];
    }
    float* out = (float*)d_out;

    cudaFuncSetAttribute(spmv_kernel,
                         cudaFuncAttributeMaxDynamicSharedMemorySize, SMEM_S);

    int nb_m2    = (M2 + 255) / 256;
    int nb_nodes = (NN + 255) / 256;
    int nb_edges = (NE + 255) / 256;
    int nb_probe = (PROBE_N + 255) / 256;
    int nb_runs  = (NRUNS + 255) / 256;

    init_kernel     <<<nb_m2, 256>>>();
    probe_kernel    <<<nb_probe, 256>>>(adj);
    count2_kernel   <<<nb_edges, 256>>>(adj);
    dis_kernel      <<<nb_nodes, 256>>>(input);
    runprep_kernel  <<<nb_runs, 256>>>();
    scan_blk_kernel <<<NRB, 1024>>>(g_runlenp, g_sR, g_bsumR, NRUNS);
    scan_tiny_kernel<<<1, 32>>>(g_bsumR, g_bexclR, NRB);
    runfix_kernel   <<<nb_runs, 256>>>();
    cursorfix_kernel<<<nb_m2, 256>>>();
    scatter16_kernel<<<nb_edges, 256>>>(adj);

    int nb_comb = (NN / 4 + 255) / 256;
    int cur = 0;   // z0 lives in g_za
    for (int i = 0; i < 49; i++) {
        int act;
        if      (i == 48) act = 4;
        else if (i == 0)  act = 0;
        else if (i == 1 || i == 11 || i == 21 || i == 31 || i == 41) act = 1;
        else if (i == 4 || i == 14 || i == 24 || i == 34 || i == 44) act = 2;
        else act = 3;
        spmv_kernel   <<<NBLOCKS, BLK_S, SMEM_S>>>(cur);
        combine_kernel<<<nb_comb, 256>>>(input, w, out, i, act, cur);
        cur ^= 1;
    }
}